// round 14
// baseline (speedup 1.0000x reference)
#include <cuda_runtime.h>
#include <cuda_bf16.h>

#define NN 100000   // nodes
#define NE 800000   // edges
#define NG 256      // graphs
#define C  96       // channels (in/hid)
#define OC 16       // out channels
#define NBLK 98     // ceil(NN/1024) for scan

// ---------------- static device scratch ----------------
__device__ __align__(16) float g_dinv[NN];
__device__ __align__(16) float g_h  [NN * C];
__device__ __align__(16) float g_act[NN * C];
__device__ __align__(16) float g_agg[NN * C];
__device__ __align__(8)  int2  g_adj[NE];
__device__ int g_deg[NN];                        // zero-init; re-zeroed by k_scan23
__device__ int g_rowptr[NN + 1];
__device__ int g_cur[NN];
__device__ int g_bsum[NBLK + 2];
__device__ int g_gstart[NG + 1];

// ---------------- packed f32x2 FMA (no broadcast needed) ----------------
__device__ __forceinline__ void ffma2(unsigned long long& d, unsigned long long a,
                                      unsigned long long b) {
    asm("fma.rn.f32x2 %0, %1, %2, %0;" : "+l"(d) : "l"(a), "l"(b));
}

// ---------------- histogram + graph segment starts (fused) ----------------
__global__ void k_hist(const int* __restrict__ ei, const int* __restrict__ batch) {
    int e = blockIdx.x * blockDim.x + threadIdx.x;
    if (e < NE) atomicAdd(&g_deg[ei[NE + e]], 1);
    if (e < NN) {
        int b = batch[e];
        int bp = (e == 0) ? -1 : batch[e - 1];
        for (int g = bp + 1; g <= b; g++) g_gstart[g] = e;
        if (e == NN - 1)
            for (int g = b + 1; g <= NG; g++) g_gstart[g] = NN;
    }
}

__global__ __launch_bounds__(1024) void k_scan1() {
    __shared__ int s[1024];
    int tid = threadIdx.x;
    int i = blockIdx.x * 1024 + tid;
    int v = (i < NN) ? g_deg[i] : 0;
    if (i < NN) g_dinv[i] = rsqrtf((float)v + 1.0f);
    s[tid] = v;
    __syncthreads();
#pragma unroll
    for (int off = 1; off < 1024; off <<= 1) {
        int t = (tid >= off) ? s[tid - off] : 0;
        __syncthreads();
        s[tid] += t;
        __syncthreads();
    }
    if (i < NN) g_rowptr[i] = s[tid] - v;
    if (tid == 1023) g_bsum[blockIdx.x] = s[1023];
}

__global__ __launch_bounds__(1024) void k_scan23() {
    __shared__ int s[128];
    int tid = threadIdx.x;
    int bid = blockIdx.x;
    if (tid < 128) s[tid] = (tid < bid) ? g_bsum[tid] : 0;
    __syncthreads();
#pragma unroll
    for (int off = 64; off > 0; off >>= 1) {
        if (tid < off) s[tid] += s[tid + off];
        __syncthreads();
    }
    int boff = s[0];
    int i = bid * 1024 + tid;
    if (i < NN) {
        g_rowptr[i] += boff;
        g_cur[i] = 0;
        g_deg[i] = 0;
    }
    if (bid == 0 && tid == 0) g_rowptr[NN] = NE;
}

__global__ void k_fill(const int* __restrict__ ei) {
    int e = blockIdx.x * blockDim.x + threadIdx.x;
    if (e >= NE) return;
    int src = ei[e];
    int dst = ei[NE + e];
    int pos = g_rowptr[dst] + atomicAdd(&g_cur[dst], 1);
    g_adj[pos] = make_int2(src, __float_as_int(g_dinv[src] * g_dinv[dst]));
}

// ---------------- GEMM: K-pair-lane FFMA2, 8 rows x 4 cols/thread ----------------
// acc lanes = (even-k partial, odd-k partial) for ONE channel; x operand is the
// raw (x_k, x_{k+1}) register pair from LDG.128 — no broadcast MOVs.
// W smem: Wp[kp*96 + j*24 + cgi] = (W[2kp][cgi*4+j], W[2kp+1][cgi*4+j]) as u64.
// Per (kp,j) warp LDS.64 addresses are 8B-contiguous over cgi: conflict-free.
__global__ __launch_bounds__(96, 6) void k_gemm(const float* __restrict__ xin,
                                                const float* __restrict__ W,
                                                int use_act) {
    __shared__ __align__(16) unsigned long long Wp[48 * 96];   // 36864 B
    const float* in = use_act ? (const float*)g_act : xin;
    int tid = threadIdx.x;

    // prologue: build interleaved W
    for (int idx = tid; idx < C * C; idx += 96) {
        int k = idx / C, c = idx - k * C;
        float* slot = reinterpret_cast<float*>(&Wp[(k >> 1) * 96 + (c & 3) * 24 + (c >> 2)]);
        slot[k & 1] = W[idx];
    }
    __syncthreads();

    int rs = tid / 24;          // 0..3  row slab (8 rows)
    int cgi = tid - rs * 24;    // 0..23 col group (4 cols)
    int row0 = blockIdx.x * 32 + rs * 8;

    unsigned long long acc[8][4];
#pragma unroll
    for (int r = 0; r < 8; r++)
#pragma unroll
        for (int c = 0; c < 4; c++) acc[r][c] = 0ull;

    for (int k4 = 0; k4 < C / 4; k4++) {
        ulonglong2 xv[8];                 // (k,k+1) packed pairs direct from LDG.128
#pragma unroll
        for (int r = 0; r < 8; r++) {
            int row = row0 + r;
            xv[r] = (row < NN)
                ? __ldg(reinterpret_cast<const ulonglong2*>(in + (size_t)row * C + k4 * 4))
                : make_ulonglong2(0ull, 0ull);
        }
#pragma unroll
        for (int half = 0; half < 2; half++) {
            const unsigned long long* wk = &Wp[(k4 * 2 + half) * 96 + cgi];
            unsigned long long w0 = wk[0];
            unsigned long long w1 = wk[24];
            unsigned long long w2 = wk[48];
            unsigned long long w3 = wk[72];
#pragma unroll
            for (int r = 0; r < 8; r++) {
                unsigned long long xp = half ? xv[r].y : xv[r].x;
                ffma2(acc[r][0], xp, w0);
                ffma2(acc[r][1], xp, w1);
                ffma2(acc[r][2], xp, w2);
                ffma2(acc[r][3], xp, w3);
            }
        }
    }

    // epilogue: lane0 + lane1 -> final channel values
#pragma unroll
    for (int r = 0; r < 8; r++) {
        int row = row0 + r;
        if (row >= NN) continue;
        float4 o;
        o.x = __uint_as_float((unsigned)acc[r][0]) + __uint_as_float((unsigned)(acc[r][0] >> 32));
        o.y = __uint_as_float((unsigned)acc[r][1]) + __uint_as_float((unsigned)(acc[r][1] >> 32));
        o.z = __uint_as_float((unsigned)acc[r][2]) + __uint_as_float((unsigned)(acc[r][2] >> 32));
        o.w = __uint_as_float((unsigned)acc[r][3]) + __uint_as_float((unsigned)(acc[r][3] >> 32));
        *reinterpret_cast<float4*>(g_h + (size_t)row * C + cgi * 4) = o;
    }
}

// ---------------- pull aggregation (fused bias + optional relu) ----------------
__global__ void k_gather(const float* __restrict__ bias, int relu) {
    int idx = blockIdx.x * blockDim.x + threadIdx.x;   // over NN*12
    if (idx >= NN * 12) return;
    int node = idx / 12;
    int c = idx - node * 12;

    const float4* hp = reinterpret_cast<const float4*>(g_h);
    float di = g_dinv[node];
    float d2 = di * di;
    float4 s0 = hp[node * 24 + 2 * c];
    float4 s1 = hp[node * 24 + 2 * c + 1];
    float4 a0 = make_float4(s0.x * d2, s0.y * d2, s0.z * d2, s0.w * d2);
    float4 a1 = make_float4(s1.x * d2, s1.y * d2, s1.z * d2, s1.w * d2);

    int beg = g_rowptr[node];
    int end = g_rowptr[node + 1];
    for (int j = beg; j < end; j++) {
        int2 rec = __ldg(&g_adj[j]);
        float cf = __int_as_float(rec.y);
        float4 v0 = hp[rec.x * 24 + 2 * c];
        float4 v1 = hp[rec.x * 24 + 2 * c + 1];
        a0.x = fmaf(v0.x, cf, a0.x); a0.y = fmaf(v0.y, cf, a0.y);
        a0.z = fmaf(v0.z, cf, a0.z); a0.w = fmaf(v0.w, cf, a0.w);
        a1.x = fmaf(v1.x, cf, a1.x); a1.y = fmaf(v1.y, cf, a1.y);
        a1.z = fmaf(v1.z, cf, a1.z); a1.w = fmaf(v1.w, cf, a1.w);
    }

    float4 b0 = __ldg(reinterpret_cast<const float4*>(bias) + 2 * c);
    float4 b1 = __ldg(reinterpret_cast<const float4*>(bias) + 2 * c + 1);
    a0.x += b0.x; a0.y += b0.y; a0.z += b0.z; a0.w += b0.w;
    a1.x += b1.x; a1.y += b1.y; a1.z += b1.z; a1.w += b1.w;

    float4* dst = relu ? reinterpret_cast<float4*>(g_act)
                       : reinterpret_cast<float4*>(g_agg);
    if (relu) {
        a0.x = fmaxf(a0.x, 0.f); a0.y = fmaxf(a0.y, 0.f);
        a0.z = fmaxf(a0.z, 0.f); a0.w = fmaxf(a0.w, 0.f);
        a1.x = fmaxf(a1.x, 0.f); a1.y = fmaxf(a1.y, 0.f);
        a1.z = fmaxf(a1.z, 0.f); a1.w = fmaxf(a1.w, 0.f);
    }
    dst[node * 24 + 2 * c] = a0;
    dst[node * 24 + 2 * c + 1] = a1;
}

// ---------------- fused mean-pool + head GEMM ----------------
__global__ __launch_bounds__(96) void k_poolhead(const float* __restrict__ Wlin,
                                                 float* __restrict__ out) {
    __shared__ float p[C];
    int g = blockIdx.x;
    int c = threadIdx.x;
    int beg = g_gstart[g], end = g_gstart[g + 1];
    float acc = 0.f;
    for (int n = beg; n < end; n++)
        acc += g_agg[(size_t)n * C + c];
    float cnt = (float)(end - beg);
    p[c] = acc / fmaxf(cnt, 1.0f);
    __syncthreads();
    if (c < OC) {
        float s = 0.f;
#pragma unroll
        for (int k = 0; k < C; k++)
            s = fmaf(p[k], __ldg(Wlin + k * OC + c), s);
        out[g * OC + c] = s;
    }
}

// ---------------- launch ----------------
extern "C" void kernel_launch(void* const* d_in, const int* in_sizes, int n_in,
                              void* d_out, int out_size) {
    const float* x     = (const float*)d_in[0];
    const int*   ei    = (const int*)d_in[1];
    const int*   batch = (const int*)d_in[2];
    const float* W1    = (const float*)d_in[3];
    const float* b1    = (const float*)d_in[4];
    const float* W2    = (const float*)d_in[5];
    const float* b2    = (const float*)d_in[6];
    const float* W3    = (const float*)d_in[7];
    const float* b3    = (const float*)d_in[8];
    const float* Wlin  = (const float*)d_in[9];
    float* out = (float*)d_out;

    const int TB = 256;
    int gE  = (NE + TB - 1) / TB;
    int gNC = (NN * 12 + TB - 1) / TB;
    int gGemm = (NN + 31) / 32;   // 3125

    k_hist<<<gE, TB>>>(ei, batch);          // 0
    k_scan1<<<NBLK, 1024>>>();              // 1
    k_scan23<<<NBLK, 1024>>>();             // 2
    k_gemm<<<gGemm, 96>>>(x, W1, 0);        // 3  <- ncu window
    k_fill<<<gE, TB>>>(ei);                 // 4

    k_gather<<<gNC, TB>>>(b1, 1);           // 5
    k_gemm<<<gGemm, 96>>>(nullptr, W2, 1);  // 6
    k_gather<<<gNC, TB>>>(b2, 1);           // 7
    k_gemm<<<gGemm, 96>>>(nullptr, W3, 1);  // 8
    k_gather<<<gNC, TB>>>(b3, 0);           // 9
    k_poolhead<<<NG, 96>>>(Wlin, out);      // 10
}

// round 15
// speedup vs baseline: 2.8205x; 2.8205x over previous
#include <cuda_runtime.h>
#include <cuda_bf16.h>

#define NN 100000   // nodes
#define NE 800000   // edges
#define NG 256      // graphs
#define C  96       // channels (in/hid)
#define OC 16       // out channels
#define NBLK 98     // ceil(NN/1024) for scan

// ---------------- static device scratch ----------------
__device__ __align__(16) float g_dinv[NN];
__device__ __align__(16) float g_h  [NN * C];
__device__ __align__(16) float g_act[NN * C];
__device__ __align__(16) float g_agg[NN * C];
__device__ __align__(8)  int2  g_adj[NE];
__device__ int g_deg[NN];                        // zero-init; re-zeroed by k_scan23
__device__ int g_rowptr[NN + 1];
__device__ int g_cur[NN];
__device__ int g_bsum[NBLK + 2];
__device__ int g_gstart[NG + 1];

// ---------------- packed f32x2 helpers (Blackwell FFMA2 via PTX) ----------------
__device__ __forceinline__ void ffma2(unsigned long long& d, unsigned long long a,
                                      unsigned long long b) {
    asm("fma.rn.f32x2 %0, %1, %2, %0;" : "+l"(d) : "l"(a), "l"(b));
}
__device__ __forceinline__ unsigned long long bcast2(float x) {
    unsigned long long r;
    asm("mov.b64 %0, {%1, %1};" : "=l"(r) : "r"(__float_as_uint(x)));
    return r;
}

// ---------------- histogram + graph segment starts (fused) ----------------
__global__ void k_hist(const int* __restrict__ ei, const int* __restrict__ batch) {
    int e = blockIdx.x * blockDim.x + threadIdx.x;
    if (e < NE) atomicAdd(&g_deg[ei[NE + e]], 1);
    if (e < NN) {
        int b = batch[e];
        int bp = (e == 0) ? -1 : batch[e - 1];
        for (int g = bp + 1; g <= b; g++) g_gstart[g] = e;
        if (e == NN - 1)
            for (int g = b + 1; g <= NG; g++) g_gstart[g] = NN;
    }
}

__global__ __launch_bounds__(1024) void k_scan1() {
    __shared__ int s[1024];
    int tid = threadIdx.x;
    int i = blockIdx.x * 1024 + tid;
    int v = (i < NN) ? g_deg[i] : 0;
    if (i < NN) g_dinv[i] = rsqrtf((float)v + 1.0f);   // +1 self-loop
    s[tid] = v;
    __syncthreads();
#pragma unroll
    for (int off = 1; off < 1024; off <<= 1) {
        int t = (tid >= off) ? s[tid - off] : 0;
        __syncthreads();
        s[tid] += t;
        __syncthreads();
    }
    if (i < NN) g_rowptr[i] = s[tid] - v;
    if (tid == 1023) g_bsum[blockIdx.x] = s[1023];
}

__global__ __launch_bounds__(1024) void k_scan23() {
    __shared__ int s[128];
    int tid = threadIdx.x;
    int bid = blockIdx.x;
    if (tid < 128) s[tid] = (tid < bid) ? g_bsum[tid] : 0;
    __syncthreads();
#pragma unroll
    for (int off = 64; off > 0; off >>= 1) {
        if (tid < off) s[tid] += s[tid + off];
        __syncthreads();
    }
    int boff = s[0];
    int i = bid * 1024 + tid;
    if (i < NN) {
        g_rowptr[i] += boff;
        g_cur[i] = 0;
        g_deg[i] = 0;            // reset for next call (scan1 already consumed it)
    }
    if (bid == 0 && tid == 0) g_rowptr[NN] = NE;
}

__global__ void k_fill(const int* __restrict__ ei) {
    int e = blockIdx.x * blockDim.x + threadIdx.x;
    if (e >= NE) return;
    int src = ei[e];
    int dst = ei[NE + e];
    int pos = g_rowptr[dst] + atomicAdd(&g_cur[dst], 1);
    g_adj[pos] = make_int2(src, __float_as_int(g_dinv[src] * g_dinv[dst]));
}

// ---------------- GEMM: 8 rows x 8 cols/thread, interleaved cols, no conflicts --
// Thread cgi owns u64 col-units {cgi, cgi+12, cgi+24, cgi+36} of plain row-major W:
// per (kk,j) the warp's 12 LDS.64 addresses are 8B-contiguous (96 B): 1 wavefront,
// zero bank conflicts, immediate offsets (+96/+192/+288 B), plain-copy prologue.
__device__ __forceinline__ float f4c(const float4& v, int k) {
    return k == 0 ? v.x : (k == 1 ? v.y : (k == 2 ? v.z : v.w));
}

__global__ __launch_bounds__(96) void k_gemm(const float* __restrict__ xin,
                                             const float* __restrict__ W,
                                             int use_act) {
    __shared__ __align__(16) float Ws[C * C];
    const float* in = use_act ? (const float*)g_act : xin;
    int tid = threadIdx.x;
    for (int i = tid; i < C * C / 4; i += 96)
        reinterpret_cast<float4*>(Ws)[i] = reinterpret_cast<const float4*>(W)[i];
    __syncthreads();

    int rs = tid / 12;         // 0..7   row slab (8 rows)
    int cgi = tid - rs * 12;   // 0..11  interleaved col group (8 cols)
    int row0 = blockIdx.x * 64 + rs * 8;

    unsigned long long acc[8][4];
#pragma unroll
    for (int r = 0; r < 8; r++)
#pragma unroll
        for (int c = 0; c < 4; c++) acc[r][c] = 0ull;

    for (int k4 = 0; k4 < C / 4; k4++) {
        float4 xv[8];
#pragma unroll
        for (int r = 0; r < 8; r++) {
            int row = row0 + r;
            xv[r] = (row < NN)
                ? __ldg(reinterpret_cast<const float4*>(in + (size_t)row * C + k4 * 4))
                : make_float4(0.f, 0.f, 0.f, 0.f);
        }
#pragma unroll
        for (int kk = 0; kk < 4; kk++) {
            const unsigned long long* wk = reinterpret_cast<const unsigned long long*>(
                &Ws[(k4 * 4 + kk) * C]) + cgi;
            unsigned long long w0 = wk[0];     // +0    conflict-free
            unsigned long long w1 = wk[12];    // +96B  immediate
            unsigned long long w2 = wk[24];    // +192B
            unsigned long long w3 = wk[36];    // +288B
#pragma unroll
            for (int r = 0; r < 8; r++) {
                unsigned long long xp = bcast2(f4c(xv[r], kk));
                ffma2(acc[r][0], xp, w0);
                ffma2(acc[r][1], xp, w1);
                ffma2(acc[r][2], xp, w2);
                ffma2(acc[r][3], xp, w3);
            }
        }
    }

    // epilogue: unit j of thread cgi = cols {2*(cgi+12j), 2*(cgi+12j)+1}
#pragma unroll
    for (int r = 0; r < 8; r++) {
        int row = row0 + r;
        if (row >= NN) continue;
        unsigned long long* hp =
            reinterpret_cast<unsigned long long*>(g_h + (size_t)row * C) + cgi;
        hp[0]  = acc[r][0];
        hp[12] = acc[r][1];
        hp[24] = acc[r][2];
        hp[36] = acc[r][3];
    }
}

// ---------------- pull aggregation (fused bias + optional relu) ----------------
__global__ void k_gather(const float* __restrict__ bias, int relu) {
    int idx = blockIdx.x * blockDim.x + threadIdx.x;   // over NN*12
    if (idx >= NN * 12) return;
    int node = idx / 12;
    int c = idx - node * 12;

    const float4* hp = reinterpret_cast<const float4*>(g_h);
    float di = g_dinv[node];
    float d2 = di * di;
    float4 s0 = hp[node * 24 + 2 * c];
    float4 s1 = hp[node * 24 + 2 * c + 1];
    float4 a0 = make_float4(s0.x * d2, s0.y * d2, s0.z * d2, s0.w * d2);
    float4 a1 = make_float4(s1.x * d2, s1.y * d2, s1.z * d2, s1.w * d2);

    int beg = g_rowptr[node];
    int end = g_rowptr[node + 1];
    for (int j = beg; j < end; j++) {
        int2 rec = __ldg(&g_adj[j]);
        float cf = __int_as_float(rec.y);
        float4 v0 = hp[rec.x * 24 + 2 * c];
        float4 v1 = hp[rec.x * 24 + 2 * c + 1];
        a0.x = fmaf(v0.x, cf, a0.x); a0.y = fmaf(v0.y, cf, a0.y);
        a0.z = fmaf(v0.z, cf, a0.z); a0.w = fmaf(v0.w, cf, a0.w);
        a1.x = fmaf(v1.x, cf, a1.x); a1.y = fmaf(v1.y, cf, a1.y);
        a1.z = fmaf(v1.z, cf, a1.z); a1.w = fmaf(v1.w, cf, a1.w);
    }

    float4 b0 = __ldg(reinterpret_cast<const float4*>(bias) + 2 * c);
    float4 b1 = __ldg(reinterpret_cast<const float4*>(bias) + 2 * c + 1);
    a0.x += b0.x; a0.y += b0.y; a0.z += b0.z; a0.w += b0.w;
    a1.x += b1.x; a1.y += b1.y; a1.z += b1.z; a1.w += b1.w;

    float4* dst = relu ? reinterpret_cast<float4*>(g_act)
                       : reinterpret_cast<float4*>(g_agg);
    if (relu) {
        a0.x = fmaxf(a0.x, 0.f); a0.y = fmaxf(a0.y, 0.f);
        a0.z = fmaxf(a0.z, 0.f); a0.w = fmaxf(a0.w, 0.f);
        a1.x = fmaxf(a1.x, 0.f); a1.y = fmaxf(a1.y, 0.f);
        a1.z = fmaxf(a1.z, 0.f); a1.w = fmaxf(a1.w, 0.f);
    }
    dst[node * 24 + 2 * c] = a0;
    dst[node * 24 + 2 * c + 1] = a1;
}

// ---------------- fused mean-pool + head GEMM ----------------
__global__ __launch_bounds__(96) void k_poolhead(const float* __restrict__ Wlin,
                                                 float* __restrict__ out) {
    __shared__ float p[C];
    int g = blockIdx.x;
    int c = threadIdx.x;
    int beg = g_gstart[g], end = g_gstart[g + 1];
    float acc = 0.f;
    for (int n = beg; n < end; n++)
        acc += g_agg[(size_t)n * C + c];
    float cnt = (float)(end - beg);
    p[c] = acc / fmaxf(cnt, 1.0f);
    __syncthreads();
    if (c < OC) {
        float s = 0.f;
#pragma unroll
        for (int k = 0; k < C; k++)
            s = fmaf(p[k], __ldg(Wlin + k * OC + c), s);
        out[g * OC + c] = s;
    }
}

// ---------------- launch ----------------
extern "C" void kernel_launch(void* const* d_in, const int* in_sizes, int n_in,
                              void* d_out, int out_size) {
    const float* x     = (const float*)d_in[0];
    const int*   ei    = (const int*)d_in[1];
    const int*   batch = (const int*)d_in[2];
    const float* W1    = (const float*)d_in[3];
    const float* b1    = (const float*)d_in[4];
    const float* W2    = (const float*)d_in[5];
    const float* b2    = (const float*)d_in[6];
    const float* W3    = (const float*)d_in[7];
    const float* b3    = (const float*)d_in[8];
    const float* Wlin  = (const float*)d_in[9];
    float* out = (float*)d_out;

    const int TB = 256;
    int gE  = (NE + TB - 1) / TB;
    int gNC = (NN * 12 + TB - 1) / TB;
    int gGemm = (NN + 63) / 64;   // 1563

    k_hist<<<gE, TB>>>(ei, batch);          // 0
    k_scan1<<<NBLK, 1024>>>();              // 1
    k_scan23<<<NBLK, 1024>>>();             // 2
    k_gemm<<<gGemm, 96>>>(x, W1, 0);        // 3  <- ncu window
    k_fill<<<gE, TB>>>(ei);                 // 4

    k_gather<<<gNC, TB>>>(b1, 1);           // 5
    k_gemm<<<gGemm, 96>>>(nullptr, W2, 1);  // 6
    k_gather<<<gNC, TB>>>(b2, 1);           // 7
    k_gemm<<<gGemm, 96>>>(nullptr, W3, 1);  // 8
    k_gather<<<gNC, TB>>>(b3, 0);           // 9
    k_poolhead<<<NG, 96>>>(Wlin, out);      // 10
}

// round 16
// speedup vs baseline: 2.8431x; 1.0080x over previous
#include <cuda_runtime.h>
#include <cuda_bf16.h>

#define NN 100000   // nodes
#define NE 800000   // edges
#define NG 256      // graphs
#define C  96       // channels (in/hid)
#define OC 16       // out channels
#define NBLK 98     // ceil(NN/1024) for scan

// ---------------- static device scratch ----------------
__device__ __align__(16) float g_dinv[NN];
__device__ __align__(16) float g_h  [NN * C];
__device__ __align__(16) float g_act[NN * C];
__device__ __align__(16) float g_agg[NN * C];
__device__ __align__(8)  int2  g_adj[NE];
__device__ int g_deg[NN];                        // zero-init; re-zeroed by k_scan23
__device__ int g_rowptr[NN + 1];
__device__ int g_cur[NN];
__device__ int g_bsum[NBLK + 2];
__device__ int g_gstart[NG + 1];

// ---------------- packed f32x2 helpers (Blackwell FFMA2 via PTX) ----------------
__device__ __forceinline__ void ffma2(unsigned long long& d, unsigned long long a,
                                      unsigned long long b) {
    asm("fma.rn.f32x2 %0, %1, %2, %0;" : "+l"(d) : "l"(a), "l"(b));
}
__device__ __forceinline__ unsigned long long bcast2(float x) {
    unsigned long long r;
    asm("mov.b64 %0, {%1, %1};" : "=l"(r) : "r"(__float_as_uint(x)));
    return r;
}

// ---------------- histogram + graph segment starts (fused) ----------------
__global__ void k_hist(const int* __restrict__ ei, const int* __restrict__ batch) {
    int e = blockIdx.x * blockDim.x + threadIdx.x;
    if (e < NE) atomicAdd(&g_deg[ei[NE + e]], 1);
    if (e < NN) {
        int b = batch[e];
        int bp = (e == 0) ? -1 : batch[e - 1];
        for (int g = bp + 1; g <= b; g++) g_gstart[g] = e;
        if (e == NN - 1)
            for (int g = b + 1; g <= NG; g++) g_gstart[g] = NN;
    }
}

__global__ __launch_bounds__(1024) void k_scan1() {
    __shared__ int s[1024];
    int tid = threadIdx.x;
    int i = blockIdx.x * 1024 + tid;
    int v = (i < NN) ? g_deg[i] : 0;
    if (i < NN) g_dinv[i] = rsqrtf((float)v + 1.0f);   // +1 self-loop
    s[tid] = v;
    __syncthreads();
#pragma unroll
    for (int off = 1; off < 1024; off <<= 1) {
        int t = (tid >= off) ? s[tid - off] : 0;
        __syncthreads();
        s[tid] += t;
        __syncthreads();
    }
    if (i < NN) g_rowptr[i] = s[tid] - v;
    if (tid == 1023) g_bsum[blockIdx.x] = s[1023];
}

__global__ __launch_bounds__(1024) void k_scan23() {
    __shared__ int s[128];
    int tid = threadIdx.x;
    int bid = blockIdx.x;
    if (tid < 128) s[tid] = (tid < bid) ? g_bsum[tid] : 0;
    __syncthreads();
#pragma unroll
    for (int off = 64; off > 0; off >>= 1) {
        if (tid < off) s[tid] += s[tid + off];
        __syncthreads();
    }
    int boff = s[0];
    int i = bid * 1024 + tid;
    if (i < NN) {
        g_rowptr[i] += boff;
        g_cur[i] = 0;
        g_deg[i] = 0;            // reset for next call (scan1 already consumed it)
    }
    if (bid == 0 && tid == 0) g_rowptr[NN] = NE;
}

__global__ void k_fill(const int* __restrict__ ei) {
    int e = blockIdx.x * blockDim.x + threadIdx.x;
    if (e >= NE) return;
    int src = ei[e];
    int dst = ei[NE + e];
    int pos = g_rowptr[dst] + atomicAdd(&g_cur[dst], 1);
    g_adj[pos] = make_int2(src, __float_as_int(g_dinv[src] * g_dinv[dst]));
}

// ---------------- GEMM: 8 rows x 8 cols/thread, interleaved cols, no conflicts --
// Thread cgi owns u64 col-units {cgi, cgi+12, cgi+24, cgi+36} of plain row-major W:
// per (kk,j) the warp's 12 LDS.64 addresses are 8B-contiguous (96 B): 1 wavefront,
// zero bank conflicts, immediate offsets. 5 blocks/SM targeted via launch_bounds
// + max smem carveout (5 x 36.9KB = 185KB <= 228KB).
__device__ __forceinline__ float f4c(const float4& v, int k) {
    return k == 0 ? v.x : (k == 1 ? v.y : (k == 2 ? v.z : v.w));
}

__global__ __launch_bounds__(96, 5) void k_gemm(const float* __restrict__ xin,
                                                const float* __restrict__ W,
                                                int use_act) {
    __shared__ __align__(16) float Ws[C * C];
    const float* in = use_act ? (const float*)g_act : xin;
    int tid = threadIdx.x;
    for (int i = tid; i < C * C / 4; i += 96)
        reinterpret_cast<float4*>(Ws)[i] = reinterpret_cast<const float4*>(W)[i];
    __syncthreads();

    int rs = tid / 12;         // 0..7   row slab (8 rows)
    int cgi = tid - rs * 12;   // 0..11  interleaved col group (8 cols)
    int row0 = blockIdx.x * 64 + rs * 8;

    unsigned long long acc[8][4];
#pragma unroll
    for (int r = 0; r < 8; r++)
#pragma unroll
        for (int c = 0; c < 4; c++) acc[r][c] = 0ull;

    for (int k4 = 0; k4 < C / 4; k4++) {
        float4 xv[8];
#pragma unroll
        for (int r = 0; r < 8; r++) {
            int row = row0 + r;
            xv[r] = (row < NN)
                ? __ldg(reinterpret_cast<const float4*>(in + (size_t)row * C + k4 * 4))
                : make_float4(0.f, 0.f, 0.f, 0.f);
        }
#pragma unroll
        for (int kk = 0; kk < 4; kk++) {
            const unsigned long long* wk = reinterpret_cast<const unsigned long long*>(
                &Ws[(k4 * 4 + kk) * C]) + cgi;
            unsigned long long w0 = wk[0];     // +0    conflict-free
            unsigned long long w1 = wk[12];    // +96B  immediate
            unsigned long long w2 = wk[24];    // +192B
            unsigned long long w3 = wk[36];    // +288B
#pragma unroll
            for (int r = 0; r < 8; r++) {
                unsigned long long xp = bcast2(f4c(xv[r], kk));
                ffma2(acc[r][0], xp, w0);
                ffma2(acc[r][1], xp, w1);
                ffma2(acc[r][2], xp, w2);
                ffma2(acc[r][3], xp, w3);
            }
        }
    }

    // epilogue: unit j of thread cgi = cols {2*(cgi+12j), 2*(cgi+12j)+1}
#pragma unroll
    for (int r = 0; r < 8; r++) {
        int row = row0 + r;
        if (row >= NN) continue;
        unsigned long long* hp =
            reinterpret_cast<unsigned long long*>(g_h + (size_t)row * C) + cgi;
        hp[0]  = acc[r][0];
        hp[12] = acc[r][1];
        hp[24] = acc[r][2];
        hp[36] = acc[r][3];
    }
}

// ---------------- pull aggregation (fused bias + optional relu) ----------------
__global__ void k_gather(const float* __restrict__ bias, int relu) {
    int idx = blockIdx.x * blockDim.x + threadIdx.x;   // over NN*12
    if (idx >= NN * 12) return;
    int node = idx / 12;
    int c = idx - node * 12;

    const float4* hp = reinterpret_cast<const float4*>(g_h);
    float di = g_dinv[node];
    float d2 = di * di;
    float4 s0 = hp[node * 24 + 2 * c];
    float4 s1 = hp[node * 24 + 2 * c + 1];
    float4 a0 = make_float4(s0.x * d2, s0.y * d2, s0.z * d2, s0.w * d2);
    float4 a1 = make_float4(s1.x * d2, s1.y * d2, s1.z * d2, s1.w * d2);

    int beg = g_rowptr[node];
    int end = g_rowptr[node + 1];
    for (int j = beg; j < end; j++) {
        int2 rec = __ldg(&g_adj[j]);
        float cf = __int_as_float(rec.y);
        float4 v0 = hp[rec.x * 24 + 2 * c];
        float4 v1 = hp[rec.x * 24 + 2 * c + 1];
        a0.x = fmaf(v0.x, cf, a0.x); a0.y = fmaf(v0.y, cf, a0.y);
        a0.z = fmaf(v0.z, cf, a0.z); a0.w = fmaf(v0.w, cf, a0.w);
        a1.x = fmaf(v1.x, cf, a1.x); a1.y = fmaf(v1.y, cf, a1.y);
        a1.z = fmaf(v1.z, cf, a1.z); a1.w = fmaf(v1.w, cf, a1.w);
    }

    float4 b0 = __ldg(reinterpret_cast<const float4*>(bias) + 2 * c);
    float4 b1 = __ldg(reinterpret_cast<const float4*>(bias) + 2 * c + 1);
    a0.x += b0.x; a0.y += b0.y; a0.z += b0.z; a0.w += b0.w;
    a1.x += b1.x; a1.y += b1.y; a1.z += b1.z; a1.w += b1.w;

    float4* dst = relu ? reinterpret_cast<float4*>(g_act)
                       : reinterpret_cast<float4*>(g_agg);
    if (relu) {
        a0.x = fmaxf(a0.x, 0.f); a0.y = fmaxf(a0.y, 0.f);
        a0.z = fmaxf(a0.z, 0.f); a0.w = fmaxf(a0.w, 0.f);
        a1.x = fmaxf(a1.x, 0.f); a1.y = fmaxf(a1.y, 0.f);
        a1.z = fmaxf(a1.z, 0.f); a1.w = fmaxf(a1.w, 0.f);
    }
    dst[node * 24 + 2 * c] = a0;
    dst[node * 24 + 2 * c + 1] = a1;
}

// ---------------- fused mean-pool + head GEMM ----------------
__global__ __launch_bounds__(96) void k_poolhead(const float* __restrict__ Wlin,
                                                 float* __restrict__ out) {
    __shared__ float p[C];
    int g = blockIdx.x;
    int c = threadIdx.x;
    int beg = g_gstart[g], end = g_gstart[g + 1];
    float acc = 0.f;
    for (int n = beg; n < end; n++)
        acc += g_agg[(size_t)n * C + c];
    float cnt = (float)(end - beg);
    p[c] = acc / fmaxf(cnt, 1.0f);
    __syncthreads();
    if (c < OC) {
        float s = 0.f;
#pragma unroll
        for (int k = 0; k < C; k++)
            s = fmaf(p[k], __ldg(Wlin + k * OC + c), s);
        out[g * OC + c] = s;
    }
}

// ---------------- launch ----------------
extern "C" void kernel_launch(void* const* d_in, const int* in_sizes, int n_in,
                              void* d_out, int out_size) {
    const float* x     = (const float*)d_in[0];
    const int*   ei    = (const int*)d_in[1];
    const int*   batch = (const int*)d_in[2];
    const float* W1    = (const float*)d_in[3];
    const float* b1    = (const float*)d_in[4];
    const float* W2    = (const float*)d_in[5];
    const float* b2    = (const float*)d_in[6];
    const float* W3    = (const float*)d_in[7];
    const float* b3    = (const float*)d_in[8];
    const float* Wlin  = (const float*)d_in[9];
    float* out = (float*)d_out;

    // max smem carveout so 5 x 36.9KB GEMM blocks fit per SM (idempotent hint)
    cudaFuncSetAttribute(k_gemm, cudaFuncAttributePreferredSharedMemoryCarveout, 100);

    const int TB = 256;
    int gE  = (NE + TB - 1) / TB;
    int gNC = (NN * 12 + TB - 1) / TB;
    int gGemm = (NN + 63) / 64;   // 1563

    k_hist<<<gE, TB>>>(ei, batch);          // 0
    k_scan1<<<NBLK, 1024>>>();              // 1
    k_scan23<<<NBLK, 1024>>>();             // 2
    k_gemm<<<gGemm, 96>>>(x, W1, 0);        // 3  <- ncu window
    k_fill<<<gE, TB>>>(ei);                 // 4

    k_gather<<<gNC, TB>>>(b1, 1);           // 5
    k_gemm<<<gGemm, 96>>>(nullptr, W2, 1);  // 6
    k_gather<<<gNC, TB>>>(b2, 1);           // 7
    k_gemm<<<gGemm, 96>>>(nullptr, W3, 1);  // 8
    k_gather<<<gNC, TB>>>(b3, 0);           // 9
    k_poolhead<<<NG, 96>>>(Wlin, out);      // 10
}

// round 17
// speedup vs baseline: 2.9644x; 1.0426x over previous
#include <cuda_runtime.h>
#include <cuda_bf16.h>

#define NN 100000   // nodes
#define NE 800000   // edges
#define NG 256      // graphs
#define C  96       // channels (in/hid)
#define OC 16       // out channels
#define NBLK 98     // ceil(NN/1024) for scan

// ---------------- static device scratch ----------------
__device__ __align__(16) float g_dinv[NN];
__device__ __align__(16) float g_h  [NN * C];
__device__ __align__(16) float g_act[NN * C];
__device__ __align__(16) float g_agg[NN * C];
__device__ __align__(8)  int2  g_adj[NE];
__device__ int g_deg[NN];                        // zero-init; re-zeroed by k_scan23
__device__ int g_rowptr[NN + 1];
__device__ int g_cur[NN];
__device__ int g_bsum[NBLK + 2];
__device__ int g_gstart[NG + 1];

// ---------------- packed f32x2 helpers (Blackwell FFMA2 via PTX) ----------------
__device__ __forceinline__ void ffma2(unsigned long long& d, unsigned long long a,
                                      unsigned long long b) {
    asm("fma.rn.f32x2 %0, %1, %2, %0;" : "+l"(d) : "l"(a), "l"(b));
}
__device__ __forceinline__ unsigned long long bcast2(float x) {
    unsigned long long r;
    asm("mov.b64 %0, {%1, %1};" : "=l"(r) : "r"(__float_as_uint(x)));
    return r;
}

// ---------------- histogram + graph segment starts (fused) ----------------
__global__ void k_hist(const int* __restrict__ ei, const int* __restrict__ batch) {
    int e = blockIdx.x * blockDim.x + threadIdx.x;
    if (e < NE) atomicAdd(&g_deg[ei[NE + e]], 1);
    if (e < NN) {
        int b = batch[e];
        int bp = (e == 0) ? -1 : batch[e - 1];
        for (int g = bp + 1; g <= b; g++) g_gstart[g] = e;
        if (e == NN - 1)
            for (int g = b + 1; g <= NG; g++) g_gstart[g] = NN;
    }
}

__global__ __launch_bounds__(1024) void k_scan1() {
    __shared__ int s[1024];
    int tid = threadIdx.x;
    int i = blockIdx.x * 1024 + tid;
    int v = (i < NN) ? g_deg[i] : 0;
    if (i < NN) g_dinv[i] = rsqrtf((float)v + 1.0f);   // +1 self-loop
    s[tid] = v;
    __syncthreads();
#pragma unroll
    for (int off = 1; off < 1024; off <<= 1) {
        int t = (tid >= off) ? s[tid - off] : 0;
        __syncthreads();
        s[tid] += t;
        __syncthreads();
    }
    if (i < NN) g_rowptr[i] = s[tid] - v;
    if (tid == 1023) g_bsum[blockIdx.x] = s[1023];
}

__global__ __launch_bounds__(1024) void k_scan23() {
    __shared__ int s[128];
    int tid = threadIdx.x;
    int bid = blockIdx.x;
    if (tid < 128) s[tid] = (tid < bid) ? g_bsum[tid] : 0;
    __syncthreads();
#pragma unroll
    for (int off = 64; off > 0; off >>= 1) {
        if (tid < off) s[tid] += s[tid + off];
        __syncthreads();
    }
    int boff = s[0];
    int i = bid * 1024 + tid;
    if (i < NN) {
        g_rowptr[i] += boff;
        g_cur[i] = 0;
        g_deg[i] = 0;            // reset for next call (scan1 already consumed it)
    }
    if (bid == 0 && tid == 0) g_rowptr[NN] = NE;
}

__global__ void k_fill(const int* __restrict__ ei) {
    int e = blockIdx.x * blockDim.x + threadIdx.x;
    if (e >= NE) return;
    int src = ei[e];
    int dst = ei[NE + e];
    int pos = g_rowptr[dst] + atomicAdd(&g_cur[dst], 1);
    g_adj[pos] = make_int2(src, __float_as_int(g_dinv[src] * g_dinv[dst]));
}

// ---------------- GEMM: 8 rows x 8 cols/thread, interleaved cols, no conflicts --
__device__ __forceinline__ float f4c(const float4& v, int k) {
    return k == 0 ? v.x : (k == 1 ? v.y : (k == 2 ? v.z : v.w));
}

__global__ __launch_bounds__(96, 5) void k_gemm(const float* __restrict__ xin,
                                                const float* __restrict__ W,
                                                int use_act) {
    __shared__ __align__(16) float Ws[C * C];
    const float* in = use_act ? (const float*)g_act : xin;
    int tid = threadIdx.x;
    for (int i = tid; i < C * C / 4; i += 96)
        reinterpret_cast<float4*>(Ws)[i] = reinterpret_cast<const float4*>(W)[i];
    __syncthreads();

    int rs = tid / 12;         // 0..7   row slab (8 rows)
    int cgi = tid - rs * 12;   // 0..11  interleaved col group (8 cols)
    int row0 = blockIdx.x * 64 + rs * 8;

    unsigned long long acc[8][4];
#pragma unroll
    for (int r = 0; r < 8; r++)
#pragma unroll
        for (int c = 0; c < 4; c++) acc[r][c] = 0ull;

    for (int k4 = 0; k4 < C / 4; k4++) {
        float4 xv[8];
#pragma unroll
        for (int r = 0; r < 8; r++) {
            int row = row0 + r;
            xv[r] = (row < NN)
                ? __ldg(reinterpret_cast<const float4*>(in + (size_t)row * C + k4 * 4))
                : make_float4(0.f, 0.f, 0.f, 0.f);
        }
#pragma unroll
        for (int kk = 0; kk < 4; kk++) {
            const unsigned long long* wk = reinterpret_cast<const unsigned long long*>(
                &Ws[(k4 * 4 + kk) * C]) + cgi;
            unsigned long long w0 = wk[0];     // +0    conflict-free
            unsigned long long w1 = wk[12];    // +96B  immediate
            unsigned long long w2 = wk[24];    // +192B
            unsigned long long w3 = wk[36];    // +288B
#pragma unroll
            for (int r = 0; r < 8; r++) {
                unsigned long long xp = bcast2(f4c(xv[r], kk));
                ffma2(acc[r][0], xp, w0);
                ffma2(acc[r][1], xp, w1);
                ffma2(acc[r][2], xp, w2);
                ffma2(acc[r][3], xp, w3);
            }
        }
    }

#pragma unroll
    for (int r = 0; r < 8; r++) {
        int row = row0 + r;
        if (row >= NN) continue;
        unsigned long long* hp =
            reinterpret_cast<unsigned long long*>(g_h + (size_t)row * C) + cgi;
        hp[0]  = acc[r][0];
        hp[12] = acc[r][1];
        hp[24] = acc[r][2];
        hp[36] = acc[r][3];
    }
}

// ---------------- pull aggregation (fused bias + optional relu) ----------------
__global__ void k_gather(const float* __restrict__ bias, int relu) {
    int idx = blockIdx.x * blockDim.x + threadIdx.x;   // over NN*12
    if (idx >= NN * 12) return;
    int node = idx / 12;
    int c = idx - node * 12;

    const float4* hp = reinterpret_cast<const float4*>(g_h);
    float di = g_dinv[node];
    float d2 = di * di;
    float4 s0 = hp[node * 24 + 2 * c];
    float4 s1 = hp[node * 24 + 2 * c + 1];
    float4 a0 = make_float4(s0.x * d2, s0.y * d2, s0.z * d2, s0.w * d2);
    float4 a1 = make_float4(s1.x * d2, s1.y * d2, s1.z * d2, s1.w * d2);

    int beg = g_rowptr[node];
    int end = g_rowptr[node + 1];
    for (int j = beg; j < end; j++) {
        int2 rec = __ldg(&g_adj[j]);
        float cf = __int_as_float(rec.y);
        float4 v0 = hp[rec.x * 24 + 2 * c];
        float4 v1 = hp[rec.x * 24 + 2 * c + 1];
        a0.x = fmaf(v0.x, cf, a0.x); a0.y = fmaf(v0.y, cf, a0.y);
        a0.z = fmaf(v0.z, cf, a0.z); a0.w = fmaf(v0.w, cf, a0.w);
        a1.x = fmaf(v1.x, cf, a1.x); a1.y = fmaf(v1.y, cf, a1.y);
        a1.z = fmaf(v1.z, cf, a1.z); a1.w = fmaf(v1.w, cf, a1.w);
    }

    float4 b0 = __ldg(reinterpret_cast<const float4*>(bias) + 2 * c);
    float4 b1 = __ldg(reinterpret_cast<const float4*>(bias) + 2 * c + 1);
    a0.x += b0.x; a0.y += b0.y; a0.z += b0.z; a0.w += b0.w;
    a1.x += b1.x; a1.y += b1.y; a1.z += b1.z; a1.w += b1.w;

    float4* dst = relu ? reinterpret_cast<float4*>(g_act)
                       : reinterpret_cast<float4*>(g_agg);
    if (relu) {
        a0.x = fmaxf(a0.x, 0.f); a0.y = fmaxf(a0.y, 0.f);
        a0.z = fmaxf(a0.z, 0.f); a0.w = fmaxf(a0.w, 0.f);
        a1.x = fmaxf(a1.x, 0.f); a1.y = fmaxf(a1.y, 0.f);
        a1.z = fmaxf(a1.z, 0.f); a1.w = fmaxf(a1.w, 0.f);
    }
    dst[node * 24 + 2 * c] = a0;
    dst[node * 24 + 2 * c + 1] = a1;
}

// ---------------- fused mean-pool + head GEMM ----------------
__global__ __launch_bounds__(96) void k_poolhead(const float* __restrict__ Wlin,
                                                 float* __restrict__ out) {
    __shared__ float p[C];
    int g = blockIdx.x;
    int c = threadIdx.x;
    int beg = g_gstart[g], end = g_gstart[g + 1];
    float acc = 0.f;
    for (int n = beg; n < end; n++)
        acc += g_agg[(size_t)n * C + c];
    float cnt = (float)(end - beg);
    p[c] = acc / fmaxf(cnt, 1.0f);
    __syncthreads();
    if (c < OC) {
        float s = 0.f;
#pragma unroll
        for (int k = 0; k < C; k++)
            s = fmaf(p[k], __ldg(Wlin + k * OC + c), s);
        out[g * OC + c] = s;
    }
}

// ---------------- launch: CSR build runs concurrently with layer-1 GEMM --------
extern "C" void kernel_launch(void* const* d_in, const int* in_sizes, int n_in,
                              void* d_out, int out_size) {
    const float* x     = (const float*)d_in[0];
    const int*   ei    = (const int*)d_in[1];
    const int*   batch = (const int*)d_in[2];
    const float* W1    = (const float*)d_in[3];
    const float* b1    = (const float*)d_in[4];
    const float* W2    = (const float*)d_in[5];
    const float* b2    = (const float*)d_in[6];
    const float* W3    = (const float*)d_in[7];
    const float* b3    = (const float*)d_in[8];
    const float* Wlin  = (const float*)d_in[9];
    float* out = (float*)d_out;

    // one-time side stream + events (created on the uncaptured correctness call;
    // only event record/wait ops appear inside graph capture — capture-legal fork/join)
    static cudaStream_t s2 = nullptr;
    static cudaEvent_t ev_fork = nullptr, ev_join = nullptr;
    if (s2 == nullptr) {
        cudaStreamCreateWithFlags(&s2, cudaStreamNonBlocking);
        cudaEventCreateWithFlags(&ev_fork, cudaEventDisableTiming);
        cudaEventCreateWithFlags(&ev_join, cudaEventDisableTiming);
    }
    cudaStream_t s0 = 0;   // harness's capture stream (legacy default)

    const int TB = 256;
    int gE  = (NE + TB - 1) / TB;
    int gNC = (NN * 12 + TB - 1) / TB;
    int gGemm = (NN + 63) / 64;   // 1563

    // fork: gemm1 on side stream, CSR build on main stream (independent)
    cudaEventRecord(ev_fork, s0);
    cudaStreamWaitEvent(s2, ev_fork, 0);
    k_gemm<<<gGemm, 96, 0, s2>>>(x, W1, 0);
    cudaEventRecord(ev_join, s2);

    k_hist<<<gE, TB, 0, s0>>>(ei, batch);
    k_scan1<<<NBLK, 1024, 0, s0>>>();
    k_scan23<<<NBLK, 1024, 0, s0>>>();
    k_fill<<<gE, TB, 0, s0>>>(ei);

    // join: gather1 needs both gemm1 (h) and fill (adj)
    cudaStreamWaitEvent(s0, ev_join, 0);

    k_gather<<<gNC, TB, 0, s0>>>(b1, 1);
    k_gemm<<<gGemm, 96, 0, s0>>>(nullptr, W2, 1);
    k_gather<<<gNC, TB, 0, s0>>>(b2, 1);
    k_gemm<<<gGemm, 96, 0, s0>>>(nullptr, W3, 1);
    k_gather<<<gNC, TB, 0, s0>>>(b3, 0);
    k_poolhead<<<NG, 96, 0, s0>>>(Wlin, out);
}